// round 2
// baseline (speedup 1.0000x reference)
#include <cuda_runtime.h>
#include <stddef.h>

// Problem constants
#define C_CH   32
#define NROW   1024
#define D_DIM  768
#define BHALF  512
#define RSTRIDE (32 * 768)   // float stride between consecutive batch rows of a channel

// ---- scratch (device globals; no allocation allowed) ----
__device__ float  g_sq[C_CH * NROW];
__device__ float  g_colpart[C_CH * 8 * D_DIM];
__device__ float  g_negc[C_CH];
__device__ double g_acc[C_CH * 3];   // per channel: Sxx, Syy, (Sxy+Syx)

__device__ __forceinline__ const float* row_base(const float* __restrict__ src,
                                                 const float* __restrict__ tgt,
                                                 int c, int i) {
    return (i < BHALF)
        ? src + ((size_t)i * 32 + c) * 768
        : tgt + ((size_t)(i - BHALF) * 32 + c) * 768;
}

// exp2 on the FMA pipe: valid for |x| < 2^22, here x in (-1, +eps]
__device__ __forceinline__ float fast_exp2(float x) {
    float r = x + 12582912.0f;              // round-to-nearest int in mantissa
    int   n = __float_as_int(r);            // 0x4B400000 + round(x); low bits carry n
    float f = x - (r - 12582912.0f);        // f in [-0.5, 0.5]
    float p = 1.5403530e-4f;
    p = fmaf(p, f, 1.3333558e-3f);
    p = fmaf(p, f, 9.6181291e-3f);
    p = fmaf(p, f, 5.5504109e-2f);
    p = fmaf(p, f, 2.4022651e-1f);
    p = fmaf(p, f, 6.9314718e-1f);
    p = fmaf(p, f, 1.0f);
    return __int_as_float(__float_as_int(p) + (n << 23));
}

// ---- P1: per-row squared norms (one warp per row) ----
__global__ void psq_kernel(const float* __restrict__ src, const float* __restrict__ tgt) {
    int c    = blockIdx.x;
    int warp = threadIdx.x >> 5, lane = threadIdx.x & 31;
    int i    = blockIdx.y * 8 + warp;
    const float4* rp = (const float4*)row_base(src, tgt, c, i);
    float s = 0.f;
#pragma unroll
    for (int j = 0; j < 6; ++j) {
        float4 v = rp[lane + 32 * j];
        s += v.x * v.x + v.y * v.y + v.z * v.z + v.w * v.w;
    }
#pragma unroll
    for (int off = 16; off; off >>= 1) s += __shfl_down_sync(0xffffffffu, s, off);
    if (lane == 0) g_sq[c * NROW + i] = s;
}

// ---- P2: partial column sums (for bandwidth) ----
__global__ void pcol_kernel(const float* __restrict__ src, const float* __restrict__ tgt) {
    int c = blockIdx.x, part = blockIdx.y;
    int t = threadIdx.x;                       // 0..191, owns float4 at d = 4t
    float4 s = make_float4(0.f, 0.f, 0.f, 0.f);
    for (int r = 0; r < 128; ++r) {
        const float4* rp = (const float4*)row_base(src, tgt, c, part * 128 + r);
        float4 v = rp[t];
        s.x += v.x; s.y += v.y; s.z += v.z; s.w += v.w;
    }
    ((float4*)g_colpart)[(c * 8 + part) * 192 + t] = s;
}

// ---- P3: bandwidth coefficient per channel + zero accumulators ----
// sum(d2) = 2n*sum(sq) - 2*||colsum||^2  (diagonal included, = 0 analytically)
__global__ void pband_kernel() {
    int c = blockIdx.x, tid = threadIdx.x;
    __shared__ double sh[256];
    double acc = 0.0;
    for (int i = tid; i < NROW; i += 256)
        acc += 2.0 * (double)NROW * (double)g_sq[c * NROW + i];
    for (int d = tid; d < D_DIM; d += 256) {
        float cs = 0.f;
#pragma unroll
        for (int p = 0; p < 8; ++p) cs += g_colpart[(c * 8 + p) * D_DIM + d];
        acc -= 2.0 * (double)cs * (double)cs;
    }
    sh[tid] = acc;
    __syncthreads();
    for (int s = 128; s > 0; s >>= 1) {
        if (tid < s) sh[tid] += sh[tid + s];
        __syncthreads();
    }
    if (tid == 0) {
        double sumd2 = sh[0];
        double bw0 = sumd2 / ((double)NROW * NROW - NROW) / 4.0;  // / KERNEL_MUL^(5//2)
        double bw4 = bw0 * 16.0;                                  // largest bandwidth
        g_negc[c] = (float)(-1.4426950408889634 / bw4);           // x = d2 * negc (log2 space)
        g_acc[c * 3 + 0] = 0.0;
        g_acc[c * 3 + 1] = 0.0;
        g_acc[c * 3 + 2] = 0.0;
    }
}

// ---- main fused kernel: symmetric GEMM tile + RBF-sum epilogue ----
#define BM  128
#define BK  16
#define PAD 4
#define LDA (BM + PAD)   // 132 floats

__global__ __launch_bounds__(256, 2) void mmd_gemm_kernel(const float* __restrict__ src,
                                                          const float* __restrict__ tgt) {
    __shared__ float As[BK][LDA];
    __shared__ float Bs[BK][LDA];
    __shared__ float red[256];

    int c = blockIdx.y;

    // tile index -> upper-triangular (bi, bj), bi <= bj, 8 row-blocks
    int bi = 0, rem = blockIdx.x;
    while (rem >= (8 - bi)) { rem -= (8 - bi); ++bi; }
    int bj = bi + rem;
    int i0 = bi * BM, j0 = bj * BM;

    int tid = threadIdx.x;
    int tx = tid & 15, ty = tid >> 4;

    const float* Abase = row_base(src, tgt, c, i0);
    const float* Bbase = row_base(src, tgt, c, j0);

    // loader mapping: tid -> (row 0..63, kvec 0..3); each thread also does row+64
    int lrow = tid >> 2;
    int lkv  = tid & 3;
    const float* pA0 = Abase + (size_t)lrow * RSTRIDE + lkv * 4;
    const float* pA1 = pA0 + (size_t)64 * RSTRIDE;
    const float* pB0 = Bbase + (size_t)lrow * RSTRIDE + lkv * 4;
    const float* pB1 = pB0 + (size_t)64 * RSTRIDE;

    float acc[8][8];
#pragma unroll
    for (int u = 0; u < 8; ++u)
#pragma unroll
        for (int v = 0; v < 8; ++v) acc[u][v] = 0.f;

    float4 ra0 = *(const float4*)(pA0);
    float4 ra1 = *(const float4*)(pA1);
    float4 rb0 = *(const float4*)(pB0);
    float4 rb1 = *(const float4*)(pB1);

    const int NK = D_DIM / BK;   // 48
    for (int ks = 0; ks < NK; ++ks) {
        // transposed store regs -> smem [k][row]
        int kb = lkv * 4;
        As[kb + 0][lrow] = ra0.x; As[kb + 1][lrow] = ra0.y;
        As[kb + 2][lrow] = ra0.z; As[kb + 3][lrow] = ra0.w;
        As[kb + 0][lrow + 64] = ra1.x; As[kb + 1][lrow + 64] = ra1.y;
        As[kb + 2][lrow + 64] = ra1.z; As[kb + 3][lrow + 64] = ra1.w;
        Bs[kb + 0][lrow] = rb0.x; Bs[kb + 1][lrow] = rb0.y;
        Bs[kb + 2][lrow] = rb0.z; Bs[kb + 3][lrow] = rb0.w;
        Bs[kb + 0][lrow + 64] = rb1.x; Bs[kb + 1][lrow + 64] = rb1.y;
        Bs[kb + 2][lrow + 64] = rb1.z; Bs[kb + 3][lrow + 64] = rb1.w;
        __syncthreads();

        if (ks + 1 < NK) {      // prefetch next K-slab (latency hidden by compute)
            int k0 = (ks + 1) * BK;
            ra0 = *(const float4*)(pA0 + k0);
            ra1 = *(const float4*)(pA1 + k0);
            rb0 = *(const float4*)(pB0 + k0);
            rb1 = *(const float4*)(pB1 + k0);
        }

#pragma unroll
        for (int k = 0; k < BK; ++k) {
            float4 a0 = *(const float4*)&As[k][ty * 8];
            float4 a1 = *(const float4*)&As[k][ty * 8 + 4];
            float4 b0 = *(const float4*)&Bs[k][tx * 8];
            float4 b1 = *(const float4*)&Bs[k][tx * 8 + 4];
            float a[8] = {a0.x, a0.y, a0.z, a0.w, a1.x, a1.y, a1.z, a1.w};
            float b[8] = {b0.x, b0.y, b0.z, b0.w, b1.x, b1.y, b1.z, b1.w};
#pragma unroll
            for (int u = 0; u < 8; ++u)
#pragma unroll
                for (int v = 0; v < 8; ++v)
                    acc[u][v] = fmaf(a[u], b[v], acc[u][v]);
        }
        __syncthreads();
    }

    // epilogue: d2 -> 5-bandwidth RBF kernel sum via one exp2 + 4 squarings
    float negc = g_negc[c];
    const float* sqc = g_sq + c * NROW;
    float sqa[8], sqb[8];
#pragma unroll
    for (int u = 0; u < 8; ++u) sqa[u] = sqc[i0 + ty * 8 + u];
#pragma unroll
    for (int v = 0; v < 8; ++v) sqb[v] = sqc[j0 + tx * 8 + v];

    float local = 0.f;
#pragma unroll
    for (int u = 0; u < 8; ++u) {
#pragma unroll
        for (int v = 0; v < 8; ++v) {
            float d2 = sqa[u] + sqb[v] - 2.0f * acc[u][v];
            float e4 = fast_exp2(d2 * negc);         // largest bandwidth
            float e3 = e4 * e4;
            float e2 = e3 * e3;
            float e1 = e2 * e2;
            float e0 = e1 * e1;                      // smallest bandwidth
            local += ((e0 + e1) + (e2 + e3)) + e4;
        }
    }

    red[tid] = local;
    __syncthreads();
    for (int s = 128; s > 0; s >>= 1) {
        if (tid < s) red[tid] += red[tid + s];
        __syncthreads();
    }
    if (tid == 0) {
        int region = (bj < 4) ? 0 : ((bi >= 4) ? 1 : 2);   // XX / YY / XY
        double w = (bi == bj) ? 1.0 : 2.0;                 // symmetry weight
        // NOTE: for the XY region w=2 makes g_acc[2] = sum_XY + sum_YX already.
        atomicAdd(&g_acc[c * 3 + region], w * (double)red[0]);
    }
}

// ---- finalize: mean over channels of (Sxx + Syy - (Sxy+Syx)) / B^2 ----
__global__ void final_kernel(float* __restrict__ out) {
    int c = threadIdx.x;   // 32 threads
    double mmd = (g_acc[c * 3 + 0] + g_acc[c * 3 + 1] - g_acc[c * 3 + 2])
                 * (1.0 / (512.0 * 512.0));
#pragma unroll
    for (int off = 16; off; off >>= 1)
        mmd += __shfl_down_sync(0xffffffffu, mmd, off);
    if (c == 0) out[0] = (float)(mmd / 32.0);
}

extern "C" void kernel_launch(void* const* d_in, const int* in_sizes, int n_in,
                              void* d_out, int out_size) {
    const float* src = (const float*)d_in[0];
    const float* tgt = (const float*)d_in[1];
    float* out = (float*)d_out;

    psq_kernel<<<dim3(32, 128), 256>>>(src, tgt);
    pcol_kernel<<<dim3(32, 8), 192>>>(src, tgt);
    pband_kernel<<<32, 256>>>();
    mmd_gemm_kernel<<<dim3(36, 32), 256>>>(src, tgt);
    final_kernel<<<1, 32>>>(out);
}

// round 5
// speedup vs baseline: 1.1424x; 1.1424x over previous
#include <cuda_runtime.h>
#include <stddef.h>
#include <stdint.h>

// Problem constants
#define C_CH   32
#define NROW   1024
#define D_DIM  768
#define BHALF  512
#define RSTRIDE (32 * 768)   // float stride between consecutive batch rows of a channel

// ---- scratch (device globals; no allocation allowed) ----
__device__ float  g_sq[C_CH * NROW];
__device__ float  g_colpart[C_CH * 8 * D_DIM];
__device__ float  g_negc[C_CH];
__device__ double g_acc[C_CH * 3];   // per channel: Sxx, Syy, (Sxy+Syx)

__device__ __forceinline__ const float* row_base(const float* __restrict__ src,
                                                 const float* __restrict__ tgt,
                                                 int c, int i) {
    return (i < BHALF)
        ? src + ((size_t)i * 32 + c) * 768
        : tgt + ((size_t)(i - BHALF) * 32 + c) * 768;
}

// exp2 on the FMA pipe: valid for |x| < 2^22, here x in (-1, +eps]
__device__ __forceinline__ float fast_exp2(float x) {
    float r = x + 12582912.0f;
    int   n = __float_as_int(r);
    float f = x - (r - 12582912.0f);
    float p = 1.5403530e-4f;
    p = fmaf(p, f, 1.3333558e-3f);
    p = fmaf(p, f, 9.6181291e-3f);
    p = fmaf(p, f, 5.5504109e-2f);
    p = fmaf(p, f, 2.4022651e-1f);
    p = fmaf(p, f, 6.9314718e-1f);
    p = fmaf(p, f, 1.0f);
    return __int_as_float(__float_as_int(p) + (n << 23));
}

// round-to-nearest tf32 (result is an f32 with low mantissa bits zero)
__device__ __forceinline__ float tf32_hi(float x) {
    uint32_t r;
    asm("cvt.rna.tf32.f32 %0, %1;" : "=r"(r) : "f"(x));
    return __uint_as_float(r);
}

// ---- P1: per-row squared norms (one warp per row) ----
__global__ void psq_kernel(const float* __restrict__ src, const float* __restrict__ tgt) {
    int c    = blockIdx.x;
    int warp = threadIdx.x >> 5, lane = threadIdx.x & 31;
    int i    = blockIdx.y * 8 + warp;
    const float4* rp = (const float4*)row_base(src, tgt, c, i);
    float s = 0.f;
#pragma unroll
    for (int j = 0; j < 6; ++j) {
        float4 v = rp[lane + 32 * j];
        s += v.x * v.x + v.y * v.y + v.z * v.z + v.w * v.w;
    }
#pragma unroll
    for (int off = 16; off; off >>= 1) s += __shfl_down_sync(0xffffffffu, s, off);
    if (lane == 0) g_sq[c * NROW + i] = s;
}

// ---- P2: partial column sums (for bandwidth) ----
__global__ void pcol_kernel(const float* __restrict__ src, const float* __restrict__ tgt) {
    int c = blockIdx.x, part = blockIdx.y;
    int t = threadIdx.x;
    float4 s = make_float4(0.f, 0.f, 0.f, 0.f);
    for (int r = 0; r < 128; ++r) {
        const float4* rp = (const float4*)row_base(src, tgt, c, part * 128 + r);
        float4 v = rp[t];
        s.x += v.x; s.y += v.y; s.z += v.z; s.w += v.w;
    }
    ((float4*)g_colpart)[(c * 8 + part) * 192 + t] = s;
}

// ---- P3: bandwidth coefficient per channel + zero accumulators ----
__global__ void pband_kernel() {
    int c = blockIdx.x, tid = threadIdx.x;
    __shared__ double sh[256];
    double acc = 0.0;
    for (int i = tid; i < NROW; i += 256)
        acc += 2.0 * (double)NROW * (double)g_sq[c * NROW + i];
    for (int d = tid; d < D_DIM; d += 256) {
        float cs = 0.f;
#pragma unroll
        for (int p = 0; p < 8; ++p) cs += g_colpart[(c * 8 + p) * D_DIM + d];
        acc -= 2.0 * (double)cs * (double)cs;
    }
    sh[tid] = acc;
    __syncthreads();
    for (int s = 128; s > 0; s >>= 1) {
        if (tid < s) sh[tid] += sh[tid + s];
        __syncthreads();
    }
    if (tid == 0) {
        double sumd2 = sh[0];
        double bw0 = sumd2 / ((double)NROW * NROW - NROW) / 4.0;
        double bw4 = bw0 * 16.0;
        g_negc[c] = (float)(-1.4426950408889634 / bw4);
        g_acc[c * 3 + 0] = 0.0;
        g_acc[c * 3 + 1] = 0.0;
        g_acc[c * 3 + 2] = 0.0;
    }
}

// ============ main kernel: 3xTF32 mma.sync GEMM + RBF epilogue ============
// Tile 128x128, BK=16. 256 threads = 8 warps (2m x 4n), warp tile 64x32 = 4x4 m16n8k8.
// Each operand kept as hi (tf32-rounded) + lo (residual); dot = hihi + hilo + lohi.
#define BM   128
#define BK   16
#define LDK  20    // BK + 4 pad floats

__device__ __forceinline__ void mma_tf32(float& c0, float& c1, float& c2, float& c3,
                                         uint32_t a0, uint32_t a1, uint32_t a2, uint32_t a3,
                                         uint32_t b0, uint32_t b1) {
    asm volatile("mma.sync.aligned.m16n8k8.row.col.f32.tf32.tf32.f32 "
                 "{%0,%1,%2,%3}, {%4,%5,%6,%7}, {%8,%9}, {%0,%1,%2,%3};"
                 : "+f"(c0), "+f"(c1), "+f"(c2), "+f"(c3)
                 : "r"(a0), "r"(a1), "r"(a2), "r"(a3), "r"(b0), "r"(b1));
}

__global__ __launch_bounds__(256) void mmd_gemm_kernel(const float* __restrict__ src,
                                                       const float* __restrict__ tgt) {
    __shared__ float AsH[BM][LDK];
    __shared__ float AsL[BM][LDK];
    __shared__ float BsH[BM][LDK];
    __shared__ float BsL[BM][LDK];
    __shared__ float sqa_sm[BM];
    __shared__ float sqb_sm[BM];
    __shared__ float red[256];

    const int c = blockIdx.y;

    // tile index -> upper-triangular (bi, bj), bi <= bj
    int bi = 0, rem = blockIdx.x;
    while (rem >= (8 - bi)) { rem -= (8 - bi); ++bi; }
    const int bj = bi + rem;
    const int i0 = bi * BM, j0 = bj * BM;

    const int tid  = threadIdx.x;
    const int wid  = tid >> 5, lane = tid & 31;
    const int g    = lane >> 2;       // groupID (0..7)
    const int tig  = lane & 3;        // thread-in-group (0..3)
    const int wm0  = (wid >> 2) * 64;
    const int wn0  = (wid & 3) * 32;

    if (tid < 128) sqa_sm[tid] = g_sq[c * NROW + i0 + tid];
    else           sqb_sm[tid - 128] = g_sq[c * NROW + j0 + (tid - 128)];

    const int lrow = tid >> 2;
    const int lkv  = tid & 3;
    const float* pA0 = row_base(src, tgt, c, i0) + (size_t)lrow * RSTRIDE + lkv * 4;
    const float* pA1 = pA0 + (size_t)64 * RSTRIDE;
    const float* pB0 = row_base(src, tgt, c, j0) + (size_t)lrow * RSTRIDE + lkv * 4;
    const float* pB1 = pB0 + (size_t)64 * RSTRIDE;

    float cacc[4][4][4];
#pragma unroll
    for (int ma = 0; ma < 4; ++ma)
#pragma unroll
        for (int na = 0; na < 4; ++na)
#pragma unroll
            for (int q = 0; q < 4; ++q) cacc[ma][na][q] = 0.f;

    float4 ra0 = *(const float4*)(pA0);
    float4 ra1 = *(const float4*)(pA1);
    float4 rb0 = *(const float4*)(pB0);
    float4 rb1 = *(const float4*)(pB1);

    const int NK = D_DIM / BK;   // 48
    for (int ks = 0; ks < NK; ++ks) {
        // split into hi/lo and store
        {
            float4 h, l;
            h.x = tf32_hi(ra0.x); h.y = tf32_hi(ra0.y); h.z = tf32_hi(ra0.z); h.w = tf32_hi(ra0.w);
            l.x = ra0.x - h.x;    l.y = ra0.y - h.y;    l.z = ra0.z - h.z;    l.w = ra0.w - h.w;
            *(float4*)&AsH[lrow][lkv * 4] = h; *(float4*)&AsL[lrow][lkv * 4] = l;
            h.x = tf32_hi(ra1.x); h.y = tf32_hi(ra1.y); h.z = tf32_hi(ra1.z); h.w = tf32_hi(ra1.w);
            l.x = ra1.x - h.x;    l.y = ra1.y - h.y;    l.z = ra1.z - h.z;    l.w = ra1.w - h.w;
            *(float4*)&AsH[lrow + 64][lkv * 4] = h; *(float4*)&AsL[lrow + 64][lkv * 4] = l;
            h.x = tf32_hi(rb0.x); h.y = tf32_hi(rb0.y); h.z = tf32_hi(rb0.z); h.w = tf32_hi(rb0.w);
            l.x = rb0.x - h.x;    l.y = rb0.y - h.y;    l.z = rb0.z - h.z;    l.w = rb0.w - h.w;
            *(float4*)&BsH[lrow][lkv * 4] = h; *(float4*)&BsL[lrow][lkv * 4] = l;
            h.x = tf32_hi(rb1.x); h.y = tf32_hi(rb1.y); h.z = tf32_hi(rb1.z); h.w = tf32_hi(rb1.w);
            l.x = rb1.x - h.x;    l.y = rb1.y - h.y;    l.z = rb1.z - h.z;    l.w = rb1.w - h.w;
            *(float4*)&BsH[lrow + 64][lkv * 4] = h; *(float4*)&BsL[lrow + 64][lkv * 4] = l;
        }
        __syncthreads();

        if (ks + 1 < NK) {
            int k0 = (ks + 1) * BK;
            ra0 = *(const float4*)(pA0 + k0);
            ra1 = *(const float4*)(pA1 + k0);
            rb0 = *(const float4*)(pB0 + k0);
            rb1 = *(const float4*)(pB1 + k0);
        }

#pragma unroll
        for (int kk = 0; kk < BK; kk += 8) {
            uint32_t afh[4][4], bfh[4][2];
            // pass 1: hi x hi
#pragma unroll
            for (int ma = 0; ma < 4; ++ma) {
                const float* ar = &AsH[wm0 + ma * 16 + g][kk + tig];
                afh[ma][0] = __float_as_uint(ar[0]);
                afh[ma][1] = __float_as_uint(ar[8 * LDK]);
                afh[ma][2] = __float_as_uint(ar[4]);
                afh[ma][3] = __float_as_uint(ar[8 * LDK + 4]);
            }
#pragma unroll
            for (int na = 0; na < 4; ++na) {
                const float* br = &BsH[wn0 + na * 8 + g][kk + tig];
                bfh[na][0] = __float_as_uint(br[0]);
                bfh[na][1] = __float_as_uint(br[4]);
            }
#pragma unroll
            for (int ma = 0; ma < 4; ++ma)
#pragma unroll
                for (int na = 0; na < 4; ++na)
                    mma_tf32(cacc[ma][na][0], cacc[ma][na][1], cacc[ma][na][2], cacc[ma][na][3],
                             afh[ma][0], afh[ma][1], afh[ma][2], afh[ma][3],
                             bfh[na][0], bfh[na][1]);
            // pass 2: hi x lo
            {
                uint32_t bfl[4][2];
#pragma unroll
                for (int na = 0; na < 4; ++na) {
                    const float* br = &BsL[wn0 + na * 8 + g][kk + tig];
                    bfl[na][0] = __float_as_uint(br[0]);
                    bfl[na][1] = __float_as_uint(br[4]);
                }
#pragma unroll
                for (int ma = 0; ma < 4; ++ma)
#pragma unroll
                    for (int na = 0; na < 4; ++na)
                        mma_tf32(cacc[ma][na][0], cacc[ma][na][1], cacc[ma][na][2], cacc[ma][na][3],
                                 afh[ma][0], afh[ma][1], afh[ma][2], afh[ma][3],
                                 bfl[na][0], bfl[na][1]);
            }
            // pass 3: lo x hi (reuse bfh, replace af with lo)
            {
                uint32_t afl[4][4];
#pragma unroll
                for (int ma = 0; ma < 4; ++ma) {
                    const float* ar = &AsL[wm0 + ma * 16 + g][kk + tig];
                    afl[ma][0] = __float_as_uint(ar[0]);
                    afl[ma][1] = __float_as_uint(ar[8 * LDK]);
                    afl[ma][2] = __float_as_uint(ar[4]);
                    afl[ma][3] = __float_as_uint(ar[8 * LDK + 4]);
                }
#pragma unroll
                for (int ma = 0; ma < 4; ++ma)
#pragma unroll
                    for (int na = 0; na < 4; ++na)
                        mma_tf32(cacc[ma][na][0], cacc[ma][na][1], cacc[ma][na][2], cacc[ma][na][3],
                                 afl[ma][0], afl[ma][1], afl[ma][2], afl[ma][3],
                                 bfh[na][0], bfh[na][1]);
            }
        }
        __syncthreads();
    }

    // ---- epilogue: d2 -> 5-bandwidth RBF sum via one exp2 + 4 squarings ----
    const float negc = g_negc[c];
    float local = 0.f;
#pragma unroll
    for (int ma = 0; ma < 4; ++ma) {
        const float sq_r0 = sqa_sm[wm0 + ma * 16 + g];
        const float sq_r1 = sqa_sm[wm0 + ma * 16 + g + 8];
#pragma unroll
        for (int na = 0; na < 4; ++na) {
            const float sq_c0 = sqb_sm[wn0 + na * 8 + tig * 2];
            const float sq_c1 = sqb_sm[wn0 + na * 8 + tig * 2 + 1];
            float d2v[4];
            d2v[0] = fmaf(-2.0f, cacc[ma][na][0], sq_r0 + sq_c0);
            d2v[1] = fmaf(-2.0f, cacc[ma][na][1], sq_r0 + sq_c1);
            d2v[2] = fmaf(-2.0f, cacc[ma][na][2], sq_r1 + sq_c0);
            d2v[3] = fmaf(-2.0f, cacc[ma][na][3], sq_r1 + sq_c1);
#pragma unroll
            for (int q = 0; q < 4; ++q) {
                float e4 = fast_exp2(d2v[q] * negc);
                float e3 = e4 * e4;
                float e2 = e3 * e3;
                float e1 = e2 * e2;
                float e0 = e1 * e1;
                local += ((e0 + e1) + (e2 + e3)) + e4;
            }
        }
    }

    red[tid] = local;
    __syncthreads();
    for (int s = 128; s > 0; s >>= 1) {
        if (tid < s) red[tid] += red[tid + s];
        __syncthreads();
    }
    if (tid == 0) {
        int region = (bj < 4) ? 0 : ((bi >= 4) ? 1 : 2);   // XX / YY / XY
        double w = (bi == bj) ? 1.0 : 2.0;                 // symmetry weight
        atomicAdd(&g_acc[c * 3 + region], w * (double)red[0]);
    }
}

// ---- finalize: mean over channels of (Sxx + Syy - (Sxy+Syx)) / B^2 ----
__global__ void final_kernel(float* __restrict__ out) {
    int c = threadIdx.x;   // 32 threads
    double mmd = (g_acc[c * 3 + 0] + g_acc[c * 3 + 1] - g_acc[c * 3 + 2])
                 * (1.0 / (512.0 * 512.0));
#pragma unroll
    for (int off = 16; off; off >>= 1)
        mmd += __shfl_down_sync(0xffffffffu, mmd, off);
    if (c == 0) out[0] = (float)(mmd / 32.0);
}

extern "C" void kernel_launch(void* const* d_in, const int* in_sizes, int n_in,
                              void* d_out, int out_size) {
    const float* src = (const float*)d_in[0];
    const float* tgt = (const float*)d_in[1];
    float* out = (float*)d_out;

    psq_kernel<<<dim3(32, 128), 256>>>(src, tgt);
    pcol_kernel<<<dim3(32, 8), 192>>>(src, tgt);
    pband_kernel<<<32, 256>>>();
    mmd_gemm_kernel<<<dim3(36, 32), 256>>>(src, tgt);
    final_kernel<<<1, 32>>>(out);
}

// round 6
// speedup vs baseline: 1.3828x; 1.2104x over previous
#include <cuda_runtime.h>
#include <stddef.h>
#include <stdint.h>

// Problem constants
#define C_CH   32
#define NROW   1024
#define D_DIM  768
#define BHALF  512
#define RSTRIDE (32 * 768)   // float stride between consecutive batch rows of a channel

// ---- scratch (device globals; no allocation allowed) ----
__device__ float  g_sq[C_CH * NROW];
__device__ float  g_colpart[C_CH * 8 * D_DIM];
__device__ float  g_negc[C_CH];
__device__ double g_acc[C_CH * 3];   // per channel: Sxx, Syy, (Sxy+Syx)

__device__ __forceinline__ const float* row_base(const float* __restrict__ src,
                                                 const float* __restrict__ tgt,
                                                 int c, int i) {
    return (i < BHALF)
        ? src + ((size_t)i * 32 + c) * 768
        : tgt + ((size_t)(i - BHALF) * 32 + c) * 768;
}

// exp2 on the FMA pipe: valid for |x| < 2^22, here x in (-1, +eps]
__device__ __forceinline__ float fast_exp2(float x) {
    float r = x + 12582912.0f;
    int   n = __float_as_int(r);
    float f = x - (r - 12582912.0f);
    float p = 1.5403530e-4f;
    p = fmaf(p, f, 1.3333558e-3f);
    p = fmaf(p, f, 9.6181291e-3f);
    p = fmaf(p, f, 5.5504109e-2f);
    p = fmaf(p, f, 2.4022651e-1f);
    p = fmaf(p, f, 6.9314718e-1f);
    p = fmaf(p, f, 1.0f);
    return __int_as_float(__float_as_int(p) + (n << 23));
}

// round-to-nearest tf32 (result is an f32 with low mantissa bits zero)
__device__ __forceinline__ float tf32_hi(float x) {
    uint32_t r;
    asm("cvt.rna.tf32.f32 %0, %1;" : "=r"(r) : "f"(x));
    return __uint_as_float(r);
}

__device__ __forceinline__ uint32_t smem_u32(const void* p) {
    uint32_t a;
    asm("{ .reg .u64 t; cvta.to.shared.u64 t, %1; cvt.u32.u64 %0, t; }" : "=r"(a) : "l"(p));
    return a;
}
__device__ __forceinline__ void cp16(uint32_t dst, const void* src) {
    asm volatile("cp.async.cg.shared.global [%0], [%1], 16;" :: "r"(dst), "l"(src));
}
#define CP_COMMIT() asm volatile("cp.async.commit_group;" ::: "memory")
#define CP_WAIT(n)  asm volatile("cp.async.wait_group %0;" :: "n"(n) : "memory")

// ---- P1: per-row squared norms (one warp per row) ----
__global__ void psq_kernel(const float* __restrict__ src, const float* __restrict__ tgt) {
    int c    = blockIdx.x;
    int warp = threadIdx.x >> 5, lane = threadIdx.x & 31;
    int i    = blockIdx.y * 8 + warp;
    const float4* rp = (const float4*)row_base(src, tgt, c, i);
    float s = 0.f;
#pragma unroll
    for (int j = 0; j < 6; ++j) {
        float4 v = rp[lane + 32 * j];
        s += v.x * v.x + v.y * v.y + v.z * v.z + v.w * v.w;
    }
#pragma unroll
    for (int off = 16; off; off >>= 1) s += __shfl_down_sync(0xffffffffu, s, off);
    if (lane == 0) g_sq[c * NROW + i] = s;
}

// ---- P2: partial column sums (for bandwidth) ----
__global__ void pcol_kernel(const float* __restrict__ src, const float* __restrict__ tgt) {
    int c = blockIdx.x, part = blockIdx.y;
    int t = threadIdx.x;
    float4 s = make_float4(0.f, 0.f, 0.f, 0.f);
    for (int r = 0; r < 128; ++r) {
        const float4* rp = (const float4*)row_base(src, tgt, c, part * 128 + r);
        float4 v = rp[t];
        s.x += v.x; s.y += v.y; s.z += v.z; s.w += v.w;
    }
    ((float4*)g_colpart)[(c * 8 + part) * 192 + t] = s;
}

// ---- P3: bandwidth coefficient per channel + zero accumulators ----
__global__ void pband_kernel() {
    int c = blockIdx.x, tid = threadIdx.x;
    __shared__ double sh[256];
    double acc = 0.0;
    for (int i = tid; i < NROW; i += 256)
        acc += 2.0 * (double)NROW * (double)g_sq[c * NROW + i];
    for (int d = tid; d < D_DIM; d += 256) {
        float cs = 0.f;
#pragma unroll
        for (int p = 0; p < 8; ++p) cs += g_colpart[(c * 8 + p) * D_DIM + d];
        acc -= 2.0 * (double)cs * (double)cs;
    }
    sh[tid] = acc;
    __syncthreads();
    for (int s = 128; s > 0; s >>= 1) {
        if (tid < s) sh[tid] += sh[tid + s];
        __syncthreads();
    }
    if (tid == 0) {
        double sumd2 = sh[0];
        double bw0 = sumd2 / ((double)NROW * NROW - NROW) / 4.0;
        double bw4 = bw0 * 16.0;
        g_negc[c] = (float)(-1.4426950408889634 / bw4);
        g_acc[c * 3 + 0] = 0.0;
        g_acc[c * 3 + 1] = 0.0;
        g_acc[c * 3 + 2] = 0.0;
    }
}

// ============ main kernel: 3xTF32 mma.sync GEMM + RBF epilogue ============
// Tile 128x128, BK=16, 2-stage cp.async pipeline. 256 threads = 8 warps (2m x 4n),
// warp tile 64x32 = 4x4 m16n8k8. Smem holds RAW fp32 tiles; hi/lo split happens
// at fragment-load time (halves LDS bytes vs storing hi+lo tiles).
#define BM   128
#define BK   16
#define LDK  20    // BK + 4 pad floats (row stride 80B: 16B-aligned, conflict-free frags)

__device__ __forceinline__ void mma_tf32(float& c0, float& c1, float& c2, float& c3,
                                         uint32_t a0, uint32_t a1, uint32_t a2, uint32_t a3,
                                         uint32_t b0, uint32_t b1) {
    asm volatile("mma.sync.aligned.m16n8k8.row.col.f32.tf32.tf32.f32 "
                 "{%0,%1,%2,%3}, {%4,%5,%6,%7}, {%8,%9}, {%0,%1,%2,%3};"
                 : "+f"(c0), "+f"(c1), "+f"(c2), "+f"(c3)
                 : "r"(a0), "r"(a1), "r"(a2), "r"(a3), "r"(b0), "r"(b1));
}

__global__ __launch_bounds__(256, 2) void mmd_gemm_kernel(const float* __restrict__ src,
                                                          const float* __restrict__ tgt) {
    __shared__ float As[2][BM][LDK];
    __shared__ float Bs[2][BM][LDK];
    __shared__ float sqa_sm[BM];
    __shared__ float sqb_sm[BM];
    __shared__ float red[256];

    const int c = blockIdx.y;

    // tile index -> upper-triangular (bi, bj), bi <= bj
    int bi = 0, rem = blockIdx.x;
    while (rem >= (8 - bi)) { rem -= (8 - bi); ++bi; }
    const int bj = bi + rem;
    const int i0 = bi * BM, j0 = bj * BM;

    const int tid  = threadIdx.x;
    const int wid  = tid >> 5, lane = tid & 31;
    const int g    = lane >> 2;       // groupID (0..7)
    const int tig  = lane & 3;        // thread-in-group (0..3)
    const int wm0  = (wid >> 2) * 64;
    const int wn0  = (wid & 3) * 32;

    if (tid < 128) sqa_sm[tid] = g_sq[c * NROW + i0 + tid];
    else           sqb_sm[tid - 128] = g_sq[c * NROW + j0 + (tid - 128)];

    // loader mapping: thread -> (row 0..63, kvec 0..3), plus row+64
    const int lrow = tid >> 2;
    const int lkv  = tid & 3;
    const float* pA0 = row_base(src, tgt, c, i0) + (size_t)lrow * RSTRIDE + lkv * 4;
    const float* pA1 = pA0 + (size_t)64 * RSTRIDE;
    const float* pB0 = row_base(src, tgt, c, j0) + (size_t)lrow * RSTRIDE + lkv * 4;
    const float* pB1 = pB0 + (size_t)64 * RSTRIDE;

    // per-thread smem cp.async destinations (stage 0; stage 1 at fixed offset)
    const uint32_t dA0 = smem_u32(&As[0][lrow][lkv * 4]);
    const uint32_t dA1 = smem_u32(&As[0][lrow + 64][lkv * 4]);
    const uint32_t dB0 = smem_u32(&Bs[0][lrow][lkv * 4]);
    const uint32_t dB1 = smem_u32(&Bs[0][lrow + 64][lkv * 4]);
    const uint32_t stA = (uint32_t)(BM * LDK * 4);   // bytes per A stage
    const uint32_t stB = (uint32_t)(BM * LDK * 4);

    float cacc[4][4][4];
#pragma unroll
    for (int ma = 0; ma < 4; ++ma)
#pragma unroll
        for (int na = 0; na < 4; ++na)
#pragma unroll
            for (int q = 0; q < 4; ++q) cacc[ma][na][q] = 0.f;

    const int NK = D_DIM / BK;   // 48

    // preload slab 0 into stage 0
    cp16(dA0, pA0); cp16(dA1, pA1); cp16(dB0, pB0); cp16(dB1, pB1);
    CP_COMMIT();

    for (int ks = 0; ks < NK; ++ks) {
        const int s = ks & 1;
        if (ks + 1 < NK) {
            const int k0 = (ks + 1) * BK;
            const uint32_t so = (uint32_t)((ks + 1) & 1) ? stA : 0u;
            cp16(dA0 + so, pA0 + k0); cp16(dA1 + so, pA1 + k0);
            cp16(dB0 + so, pB0 + k0); cp16(dB1 + so, pB1 + k0);
            CP_COMMIT();
            CP_WAIT(1);
        } else {
            CP_WAIT(0);
        }
        __syncthreads();

#pragma unroll
        for (int kk = 0; kk < BK; kk += 8) {
            // raw fragment loads (24 LDS.32/thread), then hi/lo split in registers
            float araw[4][4];
#pragma unroll
            for (int ma = 0; ma < 4; ++ma) {
                const float* ar = &As[s][wm0 + ma * 16 + g][kk + tig];
                araw[ma][0] = ar[0];
                araw[ma][1] = ar[8 * LDK];
                araw[ma][2] = ar[4];
                araw[ma][3] = ar[8 * LDK + 4];
            }
            float braw[4][2];
#pragma unroll
            for (int na = 0; na < 4; ++na) {
                const float* br = &Bs[s][wn0 + na * 8 + g][kk + tig];
                braw[na][0] = br[0];
                braw[na][1] = br[4];
            }
            uint32_t afh[4][4], afl[4][4], bfh[4][2], bfl[4][2];
#pragma unroll
            for (int ma = 0; ma < 4; ++ma)
#pragma unroll
                for (int q = 0; q < 4; ++q) {
                    float h = tf32_hi(araw[ma][q]);
                    afh[ma][q] = __float_as_uint(h);
                    afl[ma][q] = __float_as_uint(araw[ma][q] - h);
                }
#pragma unroll
            for (int na = 0; na < 4; ++na)
#pragma unroll
                for (int q = 0; q < 2; ++q) {
                    float h = tf32_hi(braw[na][q]);
                    bfh[na][q] = __float_as_uint(h);
                    bfl[na][q] = __float_as_uint(braw[na][q] - h);
                }
            // pass 1: hi x hi
#pragma unroll
            for (int ma = 0; ma < 4; ++ma)
#pragma unroll
                for (int na = 0; na < 4; ++na)
                    mma_tf32(cacc[ma][na][0], cacc[ma][na][1], cacc[ma][na][2], cacc[ma][na][3],
                             afh[ma][0], afh[ma][1], afh[ma][2], afh[ma][3],
                             bfh[na][0], bfh[na][1]);
            // pass 2: hi x lo
#pragma unroll
            for (int ma = 0; ma < 4; ++ma)
#pragma unroll
                for (int na = 0; na < 4; ++na)
                    mma_tf32(cacc[ma][na][0], cacc[ma][na][1], cacc[ma][na][2], cacc[ma][na][3],
                             afh[ma][0], afh[ma][1], afh[ma][2], afh[ma][3],
                             bfl[na][0], bfl[na][1]);
            // pass 3: lo x hi
#pragma unroll
            for (int ma = 0; ma < 4; ++ma)
#pragma unroll
                for (int na = 0; na < 4; ++na)
                    mma_tf32(cacc[ma][na][0], cacc[ma][na][1], cacc[ma][na][2], cacc[ma][na][3],
                             afl[ma][0], afl[ma][1], afl[ma][2], afl[ma][3],
                             bfh[na][0], bfh[na][1]);
        }
        __syncthreads();
    }

    // ---- epilogue: d2 -> 5-bandwidth RBF sum via one exp2 + 4 squarings ----
    const float negc = g_negc[c];
    float local = 0.f;
#pragma unroll
    for (int ma = 0; ma < 4; ++ma) {
        const float sq_r0 = sqa_sm[wm0 + ma * 16 + g];
        const float sq_r1 = sqa_sm[wm0 + ma * 16 + g + 8];
#pragma unroll
        for (int na = 0; na < 4; ++na) {
            const float sq_c0 = sqb_sm[wn0 + na * 8 + tig * 2];
            const float sq_c1 = sqb_sm[wn0 + na * 8 + tig * 2 + 1];
            float d2v[4];
            d2v[0] = fmaf(-2.0f, cacc[ma][na][0], sq_r0 + sq_c0);
            d2v[1] = fmaf(-2.0f, cacc[ma][na][1], sq_r0 + sq_c1);
            d2v[2] = fmaf(-2.0f, cacc[ma][na][2], sq_r1 + sq_c0);
            d2v[3] = fmaf(-2.0f, cacc[ma][na][3], sq_r1 + sq_c1);
#pragma unroll
            for (int q = 0; q < 4; ++q) {
                float e4 = fast_exp2(d2v[q] * negc);
                float e3 = e4 * e4;
                float e2 = e3 * e3;
                float e1 = e2 * e2;
                float e0 = e1 * e1;
                local += ((e0 + e1) + (e2 + e3)) + e4;
            }
        }
    }

    red[tid] = local;
    __syncthreads();
    for (int s = 128; s > 0; s >>= 1) {
        if (tid < s) red[tid] += red[tid + s];
        __syncthreads();
    }
    if (tid == 0) {
        int region = (bj < 4) ? 0 : ((bi >= 4) ? 1 : 2);   // XX / YY / XY
        double w = (bi == bj) ? 1.0 : 2.0;                 // symmetry weight
        atomicAdd(&g_acc[c * 3 + region], w * (double)red[0]);
    }
}

// ---- finalize: mean over channels of (Sxx + Syy - (Sxy+Syx)) / B^2 ----
__global__ void final_kernel(float* __restrict__ out) {
    int c = threadIdx.x;   // 32 threads
    double mmd = (g_acc[c * 3 + 0] + g_acc[c * 3 + 1] - g_acc[c * 3 + 2])
                 * (1.0 / (512.0 * 512.0));
#pragma unroll
    for (int off = 16; off; off >>= 1)
        mmd += __shfl_down_sync(0xffffffffu, mmd, off);
    if (c == 0) out[0] = (float)(mmd / 32.0);
}

extern "C" void kernel_launch(void* const* d_in, const int* in_sizes, int n_in,
                              void* d_out, int out_size) {
    const float* src = (const float*)d_in[0];
    const float* tgt = (const float*)d_in[1];
    float* out = (float*)d_out;

    psq_kernel<<<dim3(32, 128), 256>>>(src, tgt);
    pcol_kernel<<<dim3(32, 8), 192>>>(src, tgt);
    pband_kernel<<<32, 256>>>();
    mmd_gemm_kernel<<<dim3(36, 32), 256>>>(src, tgt);
    final_kernel<<<1, 32>>>(out);
}

// round 8
// speedup vs baseline: 1.5148x; 1.0954x over previous
#include <cuda_runtime.h>
#include <stddef.h>
#include <stdint.h>

// Problem constants
#define C_CH   32
#define NROW   1024
#define D_DIM  768
#define BHALF  512
#define RSTRIDE (32 * 768)   // float stride between consecutive batch rows of a channel

// ---- scratch (device globals; no allocation allowed) ----
__device__ float  g_sq[C_CH * NROW];
__device__ float  g_colpart[C_CH * 8 * D_DIM];
__device__ float  g_negc[C_CH];
__device__ double g_acc[C_CH * 3];   // per channel: Sxx, Syy, (Sxy+Syx)

__device__ __forceinline__ const float* row_base(const float* __restrict__ src,
                                                 const float* __restrict__ tgt,
                                                 int c, int i) {
    return (i < BHALF)
        ? src + ((size_t)i * 32 + c) * 768
        : tgt + ((size_t)(i - BHALF) * 32 + c) * 768;
}

// exp2 on the FMA pipe: valid for |x| < 2^22, here x in (-1, +eps]
__device__ __forceinline__ float fast_exp2(float x) {
    float r = x + 12582912.0f;
    int   n = __float_as_int(r);
    float f = x - (r - 12582912.0f);
    float p = 1.5403530e-4f;
    p = fmaf(p, f, 1.3333558e-3f);
    p = fmaf(p, f, 9.6181291e-3f);
    p = fmaf(p, f, 5.5504109e-2f);
    p = fmaf(p, f, 2.4022651e-1f);
    p = fmaf(p, f, 6.9314718e-1f);
    p = fmaf(p, f, 1.0f);
    return __int_as_float(__float_as_int(p) + (n << 23));
}

__device__ __forceinline__ uint32_t smem_u32(const void* p) {
    uint32_t a;
    asm("{ .reg .u64 t; cvta.to.shared.u64 t, %1; cvt.u32.u64 %0, t; }" : "=r"(a) : "l"(p));
    return a;
}
__device__ __forceinline__ void cp16(uint32_t dst, const void* src) {
    asm volatile("cp.async.cg.shared.global [%0], [%1], 16;" :: "r"(dst), "l"(src));
}
#define CP_COMMIT() asm volatile("cp.async.commit_group;" ::: "memory")
#define CP_WAIT(n)  asm volatile("cp.async.wait_group %0;" :: "n"(n) : "memory")

// ---- P1: per-row squared norms (one warp per row) ----
__global__ void psq_kernel(const float* __restrict__ src, const float* __restrict__ tgt) {
    int c    = blockIdx.x;
    int warp = threadIdx.x >> 5, lane = threadIdx.x & 31;
    int i    = blockIdx.y * 8 + warp;
    const float4* rp = (const float4*)row_base(src, tgt, c, i);
    float s = 0.f;
#pragma unroll
    for (int j = 0; j < 6; ++j) {
        float4 v = rp[lane + 32 * j];
        s += v.x * v.x + v.y * v.y + v.z * v.z + v.w * v.w;
    }
#pragma unroll
    for (int off = 16; off; off >>= 1) s += __shfl_down_sync(0xffffffffu, s, off);
    if (lane == 0) g_sq[c * NROW + i] = s;
}

// ---- P2: partial column sums (for bandwidth) ----
__global__ void pcol_kernel(const float* __restrict__ src, const float* __restrict__ tgt) {
    int c = blockIdx.x, part = blockIdx.y;
    int t = threadIdx.x;
    float4 s = make_float4(0.f, 0.f, 0.f, 0.f);
    for (int r = 0; r < 128; ++r) {
        const float4* rp = (const float4*)row_base(src, tgt, c, part * 128 + r);
        float4 v = rp[t];
        s.x += v.x; s.y += v.y; s.z += v.z; s.w += v.w;
    }
    ((float4*)g_colpart)[(c * 8 + part) * 192 + t] = s;
}

// ---- P3: bandwidth coefficient per channel + zero accumulators ----
__global__ void pband_kernel() {
    int c = blockIdx.x, tid = threadIdx.x;
    __shared__ double sh[256];
    double acc = 0.0;
    for (int i = tid; i < NROW; i += 256)
        acc += 2.0 * (double)NROW * (double)g_sq[c * NROW + i];
    for (int d = tid; d < D_DIM; d += 256) {
        float cs = 0.f;
#pragma unroll
        for (int p = 0; p < 8; ++p) cs += g_colpart[(c * 8 + p) * D_DIM + d];
        acc -= 2.0 * (double)cs * (double)cs;
    }
    sh[tid] = acc;
    __syncthreads();
    for (int s = 128; s > 0; s >>= 1) {
        if (tid < s) sh[tid] += sh[tid + s];
        __syncthreads();
    }
    if (tid == 0) {
        double sumd2 = sh[0];
        double bw0 = sumd2 / ((double)NROW * NROW - NROW) / 4.0;
        double bw4 = bw0 * 16.0;
        g_negc[c] = (float)(-1.4426950408889634 / bw4);
        g_acc[c * 3 + 0] = 0.0;
        g_acc[c * 3 + 1] = 0.0;
        g_acc[c * 3 + 2] = 0.0;
    }
}

// ============ main kernel: 3xTF32 mma.sync GEMM + RBF epilogue ============
// Tile 128x128, BK=32, 2-stage cp.async pipeline (dynamic smem). 256 threads = 8 warps
// (2m x 4n), warp tile 64x32 = 4x4 m16n8k8. Raw fp32 tiles in smem; hi/lo split at
// fragment load via AND-mask (LOP3) + exact subtract — no conversion-pipe ops.
#define BM   128
#define BK   32
#define LDK  36    // BK + 4 pad floats; (36g+tig) mod 32 hits all 32 banks

// dynamic smem layout (floats)
#define OFF_AS   0
#define OFF_BS   (2 * BM * LDK)            // 9216
#define OFF_SQA  (4 * BM * LDK)            // 18432
#define OFF_SQB  (OFF_SQA + BM)
#define OFF_RED  (OFF_SQB + BM)
#define SMEM_FLOATS (OFF_RED + 256)        // 18944
#define SMEM_BYTES  (SMEM_FLOATS * 4)      // 75776

__device__ __forceinline__ void mma_tf32(float& c0, float& c1, float& c2, float& c3,
                                         uint32_t a0, uint32_t a1, uint32_t a2, uint32_t a3,
                                         uint32_t b0, uint32_t b1) {
    asm volatile("mma.sync.aligned.m16n8k8.row.col.f32.tf32.tf32.f32 "
                 "{%0,%1,%2,%3}, {%4,%5,%6,%7}, {%8,%9}, {%0,%1,%2,%3};"
                 : "+f"(c0), "+f"(c1), "+f"(c2), "+f"(c3)
                 : "r"(a0), "r"(a1), "r"(a2), "r"(a3), "r"(b0), "r"(b1));
}

// hi = truncate-to-tf32 via mask (alu), lo = exact residual (fma pipe)
__device__ __forceinline__ void split_tf32(float a, uint32_t& hi, uint32_t& lo) {
    uint32_t h = __float_as_uint(a) & 0xFFFFE000u;
    hi = h;
    lo = __float_as_uint(a - __uint_as_float(h));
}

__global__ __launch_bounds__(256, 2) void mmd_gemm_kernel(const float* __restrict__ src,
                                                          const float* __restrict__ tgt) {
    extern __shared__ float sm[];
    float* As = sm + OFF_AS;   // [2][BM][LDK]
    float* Bs = sm + OFF_BS;
    float* sqa_sm = sm + OFF_SQA;
    float* sqb_sm = sm + OFF_SQB;
    float* red = sm + OFF_RED;

    const int c = blockIdx.y;

    // tile index -> upper-triangular (bi, bj), bi <= bj
    int bi = 0, rem = blockIdx.x;
    while (rem >= (8 - bi)) { rem -= (8 - bi); ++bi; }
    const int bj = bi + rem;
    const int i0 = bi * BM, j0 = bj * BM;

    const int tid  = threadIdx.x;
    const int wid  = tid >> 5, lane = tid & 31;
    const int g    = lane >> 2;       // groupID (0..7)
    const int tig  = lane & 3;        // thread-in-group (0..3)
    const int wm0  = (wid >> 2) * 64;
    const int wn0  = (wid & 3) * 32;

    if (tid < 128) sqa_sm[tid] = g_sq[c * NROW + i0 + tid];
    else           sqb_sm[tid - 128] = g_sq[c * NROW + j0 + (tid - 128)];

    // loader mapping: thread -> (row 0..31, kvec 0..7); covers rows {lrow, +32, +64, +96}
    const int lrow = tid >> 3;
    const int lkv  = tid & 7;
    const float* pA = row_base(src, tgt, c, i0) + (size_t)lrow * RSTRIDE + lkv * 4;
    const float* pB = row_base(src, tgt, c, j0) + (size_t)lrow * RSTRIDE + lkv * 4;

    const uint32_t dA = smem_u32(&As[lrow * LDK + lkv * 4]);
    const uint32_t dB = smem_u32(&Bs[lrow * LDK + lkv * 4]);
    const uint32_t stageB = (uint32_t)(BM * LDK * 4);   // bytes per stage
    const uint32_t rowB   = (uint32_t)(32 * LDK * 4);   // 32 rows of smem bytes
    const size_t   rowG   = (size_t)32 * RSTRIDE;

    float cacc[4][4][4];
#pragma unroll
    for (int ma = 0; ma < 4; ++ma)
#pragma unroll
        for (int na = 0; na < 4; ++na)
#pragma unroll
            for (int q = 0; q < 4; ++q) cacc[ma][na][q] = 0.f;

    const int NK = D_DIM / BK;   // 24

    // preload slab 0 into stage 0
#pragma unroll
    for (int p = 0; p < 4; ++p) {
        cp16(dA + p * rowB, pA + p * rowG);
        cp16(dB + p * rowB, pB + p * rowG);
    }
    CP_COMMIT();

    for (int ks = 0; ks < NK; ++ks) {
        const int s = ks & 1;
        if (ks + 1 < NK) {
            const int k0 = (ks + 1) * BK;
            const uint32_t so = ((ks + 1) & 1) ? stageB : 0u;
#pragma unroll
            for (int p = 0; p < 4; ++p) {
                cp16(dA + so + p * rowB, pA + k0 + p * rowG);
                cp16(dB + so + p * rowB, pB + k0 + p * rowG);
            }
            CP_COMMIT();
            CP_WAIT(1);
        } else {
            CP_WAIT(0);
        }
        __syncthreads();

        const float* Ast = As + s * BM * LDK;
        const float* Bst = Bs + s * BM * LDK;
#pragma unroll
        for (int kk = 0; kk < BK; kk += 8) {
            // raw fragment loads, then LOP3/FADD split in registers
            uint32_t afh[4][4], afl[4][4], bfh[4][2], bfl[4][2];
#pragma unroll
            for (int ma = 0; ma < 4; ++ma) {
                const float* ar = &Ast[(wm0 + ma * 16 + g) * LDK + kk + tig];
                split_tf32(ar[0],           afh[ma][0], afl[ma][0]);
                split_tf32(ar[8 * LDK],     afh[ma][1], afl[ma][1]);
                split_tf32(ar[4],           afh[ma][2], afl[ma][2]);
                split_tf32(ar[8 * LDK + 4], afh[ma][3], afl[ma][3]);
            }
#pragma unroll
            for (int na = 0; na < 4; ++na) {
                const float* br = &Bst[(wn0 + na * 8 + g) * LDK + kk + tig];
                split_tf32(br[0], bfh[na][0], bfl[na][0]);
                split_tf32(br[4], bfh[na][1], bfl[na][1]);
            }
            // pass 1: hi x hi
#pragma unroll
            for (int ma = 0; ma < 4; ++ma)
#pragma unroll
                for (int na = 0; na < 4; ++na)
                    mma_tf32(cacc[ma][na][0], cacc[ma][na][1], cacc[ma][na][2], cacc[ma][na][3],
                             afh[ma][0], afh[ma][1], afh[ma][2], afh[ma][3],
                             bfh[na][0], bfh[na][1]);
            // pass 2: hi x lo
#pragma unroll
            for (int ma = 0; ma < 4; ++ma)
#pragma unroll
                for (int na = 0; na < 4; ++na)
                    mma_tf32(cacc[ma][na][0], cacc[ma][na][1], cacc[ma][na][2], cacc[ma][na][3],
                             afh[ma][0], afh[ma][1], afh[ma][2], afh[ma][3],
                             bfl[na][0], bfl[na][1]);
            // pass 3: lo x hi
#pragma unroll
            for (int ma = 0; ma < 4; ++ma)
#pragma unroll
                for (int na = 0; na < 4; ++na)
                    mma_tf32(cacc[ma][na][0], cacc[ma][na][1], cacc[ma][na][2], cacc[ma][na][3],
                             afl[ma][0], afl[ma][1], afl[ma][2], afl[ma][3],
                             bfh[na][0], bfh[na][1]);
        }
        __syncthreads();
    }

    // ---- epilogue: d2 -> 5-bandwidth RBF sum via one exp2 + 4 squarings ----
    const float negc = g_negc[c];
    float local = 0.f;
#pragma unroll
    for (int ma = 0; ma < 4; ++ma) {
        const float sq_r0 = sqa_sm[wm0 + ma * 16 + g];
        const float sq_r1 = sqa_sm[wm0 + ma * 16 + g + 8];
#pragma unroll
        for (int na = 0; na < 4; ++na) {
            const float sq_c0 = sqb_sm[wn0 + na * 8 + tig * 2];
            const float sq_c1 = sqb_sm[wn0 + na * 8 + tig * 2 + 1];
            float d2v[4];
            d2v[0] = fmaf(-2.0f, cacc[ma][na][0], sq_r0 + sq_c0);
            d2v[1] = fmaf(-2.0f, cacc[ma][na][1], sq_r0 + sq_c1);
            d2v[2] = fmaf(-2.0f, cacc[ma][na][2], sq_r1 + sq_c0);
            d2v[3] = fmaf(-2.0f, cacc[ma][na][3], sq_r1 + sq_c1);
#pragma unroll
            for (int q = 0; q < 4; ++q) {
                float e4 = fast_exp2(d2v[q] * negc);
                float e3 = e4 * e4;
                float e2 = e3 * e3;
                float e1 = e2 * e2;
                float e0 = e1 * e1;
                local += ((e0 + e1) + (e2 + e3)) + e4;
            }
        }
    }

    red[tid] = local;
    __syncthreads();
    for (int s = 128; s > 0; s >>= 1) {
        if (tid < s) red[tid] += red[tid + s];
        __syncthreads();
    }
    if (tid == 0) {
        int region = (bj < 4) ? 0 : ((bi >= 4) ? 1 : 2);   // XX / YY / XY
        double w = (bi == bj) ? 1.0 : 2.0;                 // symmetry weight
        atomicAdd(&g_acc[c * 3 + region], w * (double)red[0]);
    }
}

// ---- finalize: mean over channels of (Sxx + Syy - (Sxy+Syx)) / B^2 ----
__global__ void final_kernel(float* __restrict__ out) {
    int c = threadIdx.x;   // 32 threads
    double mmd = (g_acc[c * 3 + 0] + g_acc[c * 3 + 1] - g_acc[c * 3 + 2])
                 * (1.0 / (512.0 * 512.0));
#pragma unroll
    for (int off = 16; off; off >>= 1)
        mmd += __shfl_down_sync(0xffffffffu, mmd, off);
    if (c == 0) out[0] = (float)(mmd / 32.0);
}

extern "C" void kernel_launch(void* const* d_in, const int* in_sizes, int n_in,
                              void* d_out, int out_size) {
    const float* src = (const float*)d_in[0];
    const float* tgt = (const float*)d_in[1];
    float* out = (float*)d_out;

    cudaFuncSetAttribute(mmd_gemm_kernel, cudaFuncAttributeMaxDynamicSharedMemorySize, SMEM_BYTES);

    psq_kernel<<<dim3(32, 128), 256>>>(src, tgt);
    pcol_kernel<<<dim3(32, 8), 192>>>(src, tgt);
    pband_kernel<<<32, 256>>>();
    mmd_gemm_kernel<<<dim3(36, 32), 256, SMEM_BYTES>>>(src, tgt);
    final_kernel<<<1, 32>>>(out);
}

// round 11
// speedup vs baseline: 2.1876x; 1.4442x over previous
#include <cuda_runtime.h>
#include <stddef.h>
#include <stdint.h>

// Problem constants
#define C_CH   32
#define NROW   1024
#define D_DIM  768
#define BHALF  512
#define RSTRIDE (32 * 768)   // float stride between consecutive batch rows of a channel

// ---- scratch (device globals; no allocation allowed) ----
__device__ float  g_sq[C_CH * NROW];
__device__ float  g_colpart[C_CH * 8 * D_DIM];
__device__ float  g_negc[C_CH];
__device__ double g_acc[C_CH * 3];   // per channel: Sxx, Syy, (Sxy+Syx)

__device__ __forceinline__ const float* row_base(const float* __restrict__ src,
                                                 const float* __restrict__ tgt,
                                                 int c, int i) {
    return (i < BHALF)
        ? src + ((size_t)i * 32 + c) * 768
        : tgt + ((size_t)(i - BHALF) * 32 + c) * 768;
}

// exp2 on the FMA pipe: valid for |x| < 2^22, here x in (-1, +eps]
__device__ __forceinline__ float fast_exp2(float x) {
    float r = x + 12582912.0f;
    int   n = __float_as_int(r);
    float f = x - (r - 12582912.0f);
    float p = 1.5403530e-4f;
    p = fmaf(p, f, 1.3333558e-3f);
    p = fmaf(p, f, 9.6181291e-3f);
    p = fmaf(p, f, 5.5504109e-2f);
    p = fmaf(p, f, 2.4022651e-1f);
    p = fmaf(p, f, 6.9314718e-1f);
    p = fmaf(p, f, 1.0f);
    return __int_as_float(__float_as_int(p) + (n << 23));
}

__device__ __forceinline__ uint32_t smem_u32(const void* p) {
    uint32_t a;
    asm("{ .reg .u64 t; cvta.to.shared.u64 t, %1; cvt.u32.u64 %0, t; }" : "=r"(a) : "l"(p));
    return a;
}
__device__ __forceinline__ void cp16(uint32_t dst, const void* src) {
    asm volatile("cp.async.cg.shared.global [%0], [%1], 16;" :: "r"(dst), "l"(src));
}
#define CP_COMMIT() asm volatile("cp.async.commit_group;" ::: "memory")
#define CP_WAIT(n)  asm volatile("cp.async.wait_group %0;" :: "n"(n) : "memory")

// ---- P1: per-row squared norms (one warp per row) ----
__global__ void psq_kernel(const float* __restrict__ src, const float* __restrict__ tgt) {
    int c    = blockIdx.x;
    int warp = threadIdx.x >> 5, lane = threadIdx.x & 31;
    int i    = blockIdx.y * 8 + warp;
    const float4* rp = (const float4*)row_base(src, tgt, c, i);
    float s = 0.f;
#pragma unroll
    for (int j = 0; j < 6; ++j) {
        float4 v = rp[lane + 32 * j];
        s += v.x * v.x + v.y * v.y + v.z * v.z + v.w * v.w;
    }
#pragma unroll
    for (int off = 16; off; off >>= 1) s += __shfl_down_sync(0xffffffffu, s, off);
    if (lane == 0) g_sq[c * NROW + i] = s;
}

// ---- P2: partial column sums (for bandwidth) ----
__global__ void pcol_kernel(const float* __restrict__ src, const float* __restrict__ tgt) {
    int c = blockIdx.x, part = blockIdx.y;
    int t = threadIdx.x;
    float4 s = make_float4(0.f, 0.f, 0.f, 0.f);
    for (int r = 0; r < 128; ++r) {
        const float4* rp = (const float4*)row_base(src, tgt, c, part * 128 + r);
        float4 v = rp[t];
        s.x += v.x; s.y += v.y; s.z += v.z; s.w += v.w;
    }
    ((float4*)g_colpart)[(c * 8 + part) * 192 + t] = s;
}

// ---- P3: bandwidth coefficient per channel + zero accumulators ----
__global__ void pband_kernel() {
    int c = blockIdx.x, tid = threadIdx.x;
    __shared__ double sh[256];
    double acc = 0.0;
    for (int i = tid; i < NROW; i += 256)
        acc += 2.0 * (double)NROW * (double)g_sq[c * NROW + i];
    for (int d = tid; d < D_DIM; d += 256) {
        float cs = 0.f;
#pragma unroll
        for (int p = 0; p < 8; ++p) cs += g_colpart[(c * 8 + p) * D_DIM + d];
        acc -= 2.0 * (double)cs * (double)cs;
    }
    sh[tid] = acc;
    __syncthreads();
    for (int s = 128; s > 0; s >>= 1) {
        if (tid < s) sh[tid] += sh[tid + s];
        __syncthreads();
    }
    if (tid == 0) {
        double sumd2 = sh[0];
        double bw0 = sumd2 / ((double)NROW * NROW - NROW) / 4.0;
        double bw4 = bw0 * 16.0;
        g_negc[c] = (float)(-1.4426950408889634 / bw4);
        g_acc[c * 3 + 0] = 0.0;
        g_acc[c * 3 + 1] = 0.0;
        g_acc[c * 3 + 2] = 0.0;
    }
}

// ============ main kernel: fp16x3 mma.sync m16n8k16 GEMM + RBF epilogue ============
// Tile 128x128, BK=32, 2-stage cp.async pipeline (raw fp32 in smem). 256 threads =
// 8 warps (2m x 4n), warp tile 64x32 = 4x4 m16n8k16 atoms. Each operand fragment is
// split in registers into fp16 hi (10-bit trunc, exact) + fp16 lo (residual);
// dot = hi*hi + hi*lo + lo*hi at the fp16 tensor rate (2x tf32). Scheme error ~2^-22.
#define BM   128
#define BK   32
#define LDK  40    // fp32 words/row; float2 frag loads: word (40g + 2tig) conflict-free

// dynamic smem layout (floats)
#define OFF_AS   0
#define OFF_BS   (2 * BM * LDK)            // 10240
#define OFF_SQA  (4 * BM * LDK)            // 20480
#define OFF_SQB  (OFF_SQA + BM)
#define OFF_RED  (OFF_SQB + BM)
#define SMEM_FLOATS (OFF_RED + 256)        // 20992
#define SMEM_BYTES  (SMEM_FLOATS * 4)      // 83968

__device__ __forceinline__ void mma_f16(float& c0, float& c1, float& c2, float& c3,
                                        uint32_t a0, uint32_t a1, uint32_t a2, uint32_t a3,
                                        uint32_t b0, uint32_t b1) {
    asm volatile("mma.sync.aligned.m16n8k16.row.col.f32.f16.f16.f32 "
                 "{%0,%1,%2,%3}, {%4,%5,%6,%7}, {%8,%9}, {%0,%1,%2,%3};"
                 : "+f"(c0), "+f"(c1), "+f"(c2), "+f"(c3)
                 : "r"(a0), "r"(a1), "r"(a2), "r"(a3), "r"(b0), "r"(b1));
}

// split float2 -> fp16 hi half2 + fp16 lo half2.
// hi = f32 masked to 10 mantissa bits (exactly fp16-representable); lo = exact residual.
__device__ __forceinline__ void split2(float2 v, uint32_t& h2, uint32_t& l2) {
    float h0 = __uint_as_float(__float_as_uint(v.x) & 0xFFFFE000u);
    float h1 = __uint_as_float(__float_as_uint(v.y) & 0xFFFFE000u);
    float l0 = v.x - h0;
    float l1 = v.y - h1;
    asm("cvt.rn.f16x2.f32 %0, %1, %2;" : "=r"(h2) : "f"(h1), "f"(h0));  // {hi: h1, lo: h0}
    asm("cvt.rn.f16x2.f32 %0, %1, %2;" : "=r"(l2) : "f"(l1), "f"(l0));
}

__global__ __launch_bounds__(256, 2) void mmd_gemm_kernel(const float* __restrict__ src,
                                                          const float* __restrict__ tgt) {
    extern __shared__ float sm[];
    float* As = sm + OFF_AS;   // [2][BM][LDK] raw fp32
    float* Bs = sm + OFF_BS;
    float* sqa_sm = sm + OFF_SQA;
    float* sqb_sm = sm + OFF_SQB;
    float* red = sm + OFF_RED;

    const int c = blockIdx.y;

    // tile index -> upper-triangular (bi, bj), bi <= bj
    int bi = 0, rem = blockIdx.x;
    while (rem >= (8 - bi)) { rem -= (8 - bi); ++bi; }
    const int bj = bi + rem;
    const int i0 = bi * BM, j0 = bj * BM;

    const int tid  = threadIdx.x;
    const int wid  = tid >> 5, lane = tid & 31;
    const int g    = lane >> 2;       // groupID (0..7)
    const int tig  = lane & 3;        // thread-in-group (0..3)
    const int wm0  = (wid >> 2) * 64;
    const int wn0  = (wid & 3) * 32;

    if (tid < 128) sqa_sm[tid] = g_sq[c * NROW + i0 + tid];
    else           sqb_sm[tid - 128] = g_sq[c * NROW + j0 + (tid - 128)];

    // loader mapping: thread -> (row 0..31, kvec 0..7); covers rows {lrow, +32, +64, +96}
    const int lrow = tid >> 3;
    const int lkv  = tid & 7;
    const float* pA = row_base(src, tgt, c, i0) + (size_t)lrow * RSTRIDE + lkv * 4;
    const float* pB = row_base(src, tgt, c, j0) + (size_t)lrow * RSTRIDE + lkv * 4;

    const uint32_t dA = smem_u32(&As[lrow * LDK + lkv * 4]);
    const uint32_t dB = smem_u32(&Bs[lrow * LDK + lkv * 4]);
    const uint32_t stageB = (uint32_t)(BM * LDK * 4);   // bytes per stage
    const uint32_t rowB   = (uint32_t)(32 * LDK * 4);   // 32 smem rows in bytes
    const size_t   rowG   = (size_t)32 * RSTRIDE;

    float cacc[4][4][4];
#pragma unroll
    for (int ma = 0; ma < 4; ++ma)
#pragma unroll
        for (int na = 0; na < 4; ++na)
#pragma unroll
            for (int q = 0; q < 4; ++q) cacc[ma][na][q] = 0.f;

    const int NK = D_DIM / BK;   // 24

    // preload slab 0 into stage 0
#pragma unroll
    for (int p = 0; p < 4; ++p) {
        cp16(dA + p * rowB, pA + p * rowG);
        cp16(dB + p * rowB, pB + p * rowG);
    }
    CP_COMMIT();

    for (int ks = 0; ks < NK; ++ks) {
        const int s = ks & 1;
        if (ks + 1 < NK) {
            const int k0 = (ks + 1) * BK;
            const uint32_t so = ((ks + 1) & 1) ? stageB : 0u;
#pragma unroll
            for (int p = 0; p < 4; ++p) {
                cp16(dA + so + p * rowB, pA + k0 + p * rowG);
                cp16(dB + so + p * rowB, pB + k0 + p * rowG);
            }
            CP_COMMIT();
            CP_WAIT(1);
        } else {
            CP_WAIT(0);
        }
        __syncthreads();

        const float* Ast = As + s * BM * LDK;
        const float* Bst = Bs + s * BM * LDK;
#pragma unroll
        for (int kk = 0; kk < BK; kk += 16) {
            // fp32 fragment loads (LDS.64) + in-register fp16 hi/lo split
            uint32_t ah[4][4], al[4][4], bh[4][2], bl[4][2];
#pragma unroll
            for (int ma = 0; ma < 4; ++ma) {
                const float* ar = &Ast[(wm0 + ma * 16 + g) * LDK + kk + 2 * tig];
                split2(*(const float2*)(ar),             ah[ma][0], al[ma][0]);  // row g,   k lo
                split2(*(const float2*)(ar + 8 * LDK),   ah[ma][1], al[ma][1]);  // row g+8, k lo
                split2(*(const float2*)(ar + 8),         ah[ma][2], al[ma][2]);  // row g,   k hi
                split2(*(const float2*)(ar + 8 * LDK + 8), ah[ma][3], al[ma][3]);// row g+8, k hi
            }
#pragma unroll
            for (int na = 0; na < 4; ++na) {
                const float* br = &Bst[(wn0 + na * 8 + g) * LDK + kk + 2 * tig];
                split2(*(const float2*)(br),     bh[na][0], bl[na][0]);          // k lo
                split2(*(const float2*)(br + 8), bh[na][1], bl[na][1]);          // k hi
            }
            // pass 1: hi x hi
#pragma unroll
            for (int ma = 0; ma < 4; ++ma)
#pragma unroll
                for (int na = 0; na < 4; ++na)
                    mma_f16(cacc[ma][na][0], cacc[ma][na][1], cacc[ma][na][2], cacc[ma][na][3],
                            ah[ma][0], ah[ma][1], ah[ma][2], ah[ma][3],
                            bh[na][0], bh[na][1]);
            // pass 2: hi x lo
#pragma unroll
            for (int ma = 0; ma < 4; ++ma)
#pragma unroll
                for (int na = 0; na < 4; ++na)
                    mma_f16(cacc[ma][na][0], cacc[ma][na][1], cacc[ma][na][2], cacc[ma][na][3],
                            ah[ma][0], ah[ma][1], ah[ma][2], ah[ma][3],
                            bl[na][0], bl[na][1]);
            // pass 3: lo x hi
#pragma unroll
            for (int ma = 0; ma < 4; ++ma)
#pragma unroll
                for (int na = 0; na < 4; ++na)
                    mma_f16(cacc[ma][na][0], cacc[ma][na][1], cacc[ma][na][2], cacc[ma][na][3],
                            al[ma][0], al[ma][1], al[ma][2], al[ma][3],
                            bh[na][0], bh[na][1]);
        }
        __syncthreads();
    }

    // ---- epilogue: d2 -> 5-bandwidth RBF sum via one exp2 + 4 squarings ----
    // D-fragment layout identical to tf32 path: c0=(g,2tig) c1=(g,2tig+1) c2=(g+8,2tig) c3=(g+8,2tig+1)
    const float negc = g_negc[c];
    float local = 0.f;
#pragma unroll
    for (int ma = 0; ma < 4; ++ma) {
        const float sq_r0 = sqa_sm[wm0 + ma * 16 + g];
        const float sq_r1 = sqa_sm[wm0 + ma * 16 + g + 8];
#pragma unroll
        for (int na = 0; na < 4; ++na) {
            const float sq_c0 = sqb_sm[wn0 + na * 8 + tig * 2];
            const float sq_c1 = sqb_sm[wn0 + na * 8 + tig * 2 + 1];
            float d2v[4];
            d2v[0] = fmaf(-2.0f, cacc[ma][na][0], sq_r0 + sq_c0);
            d2v[1] = fmaf(-2.0f, cacc[ma][na][1], sq_r0 + sq_c1);
            d2v[2] = fmaf(-2.0f, cacc[ma][na][2], sq_r1 + sq_c0);
            d2v[3] = fmaf(-2.0f, cacc[ma][na][3], sq_r1 + sq_c1);
#pragma unroll
            for (int q = 0; q < 4; ++q) {
                float e4 = fast_exp2(d2v[q] * negc);
                float e3 = e4 * e4;
                float e2 = e3 * e3;
                float e1 = e2 * e2;
                float e0 = e1 * e1;
                local += ((e0 + e1) + (e2 + e3)) + e4;
            }
        }
    }

    red[tid] = local;
    __syncthreads();
    for (int s = 128; s > 0; s >>= 1) {
        if (tid < s) red[tid] += red[tid + s];
        __syncthreads();
    }
    if (tid == 0) {
        int region = (bj < 4) ? 0 : ((bi >= 4) ? 1 : 2);   // XX / YY / XY
        double w = (bi == bj) ? 1.0 : 2.0;                 // symmetry weight
        atomicAdd(&g_acc[c * 3 + region], w * (double)red[0]);
    }
}

// ---- finalize: mean over channels of (Sxx + Syy - (Sxy+Syx)) / B^2 ----
__global__ void final_kernel(float* __restrict__ out) {
    int c = threadIdx.x;   // 32 threads
    double mmd = (g_acc[c * 3 + 0] + g_acc[c * 3 + 1] - g_acc[c * 3 + 2])
                 * (1.0 / (512.0 * 512.0));
#pragma unroll
    for (int off = 16; off; off >>= 1)
        mmd += __shfl_down_sync(0xffffffffu, mmd, off);
    if (c == 0) out[0] = (float)(mmd / 32.0);
}

extern "C" void kernel_launch(void* const* d_in, const int* in_sizes, int n_in,
                              void* d_out, int out_size) {
    const float* src = (const float*)d_in[0];
    const float* tgt = (const float*)d_in[1];
    float* out = (float*)d_out;

    cudaFuncSetAttribute(mmd_gemm_kernel, cudaFuncAttributeMaxDynamicSharedMemorySize, SMEM_BYTES);

    psq_kernel<<<dim3(32, 128), 256>>>(src, tgt);
    pcol_kernel<<<dim3(32, 8), 192>>>(src, tgt);
    pband_kernel<<<32, 256>>>();
    mmd_gemm_kernel<<<dim3(36, 32), 256, SMEM_BYTES>>>(src, tgt);
    final_kernel<<<1, 32>>>(out);
}